// round 3
// baseline (speedup 1.0000x reference)
#include <cuda_runtime.h>
#include <cstdint>

#define B_  8
#define H_  8
#define NQ_ 1024
#define NKV_ 2048
#define D_  512
#define HD_ 64

// ---------------- scratch (static __device__, no allocs) ----------------
// g_Q, g_K: [b][h][nseq][64], hd-interleaved in 8-chunks, tf32-pre-rounded
// g_VT:     [b][h][64][nkv],  kv-interleaved in 8-chunks, tf32-pre-rounded
__device__ float g_Q [B_ * H_ * NQ_  * HD_];   // 16 MB
__device__ float g_K [B_ * H_ * NKV_ * HD_];   // 32 MB
__device__ float g_VT[B_ * H_ * HD_ * NKV_];   // 32 MB
__device__ float g_AO[B_ * NQ_ * D_];          // 16 MB

// ---------------- PTX helpers ----------------
__device__ __forceinline__ uint32_t f2tf32(float x) {
    uint32_t r;
    asm("cvt.rna.tf32.f32 %0, %1;" : "=r"(r) : "f"(x));
    return r;
}
__device__ __forceinline__ float tfr(float x) {           // round to tf32, keep as float
    return __uint_as_float(f2tf32(x));
}

__device__ __forceinline__ void mma_tf32(float* c, const uint32_t* a, uint32_t b0, uint32_t b1) {
    asm volatile(
        "mma.sync.aligned.m16n8k8.row.col.f32.tf32.tf32.f32 "
        "{%0,%1,%2,%3}, {%4,%5,%6,%7}, {%8,%9}, {%0,%1,%2,%3};"
        : "+f"(c[0]), "+f"(c[1]), "+f"(c[2]), "+f"(c[3])
        : "r"(a[0]), "r"(a[1]), "r"(a[2]), "r"(a[3]), "r"(b0), "r"(b1));
}

__device__ __forceinline__ void cp16(void* dst, const void* src) {
    uint32_t d = (uint32_t)__cvta_generic_to_shared(dst);
    asm volatile("cp.async.cg.shared.global [%0], [%1], 16;" :: "r"(d), "l"(src));
}
#define CP_COMMIT() asm volatile("cp.async.commit_group;")

// interleave position within an 8-chunk: [v0,v4,v1,v5,v2,v6,v3,v7]
__device__ __forceinline__ int ilpos(int j) { return (j < 4) ? 2 * j : 2 * j - 7; }

// =======================================================================
// GEMM: out[m][n] = sum_k A[m][k] * W[n][k]   (M x 512 @ 512 x 512)
// DST: 0 -> g_Q (head-split, il, tf32), 1 -> g_K (same), 2 -> g_VT
//      (transposed, kv-il, tf32), 4 -> plain fp32 out, A = g_AO.
// =======================================================================
#define GSTR 40   // 128x32 tile, row stride 40 floats (mod 32 words == 8)

template<int DST>
__global__ __launch_bounds__(256, 2)
void gemm_tf32(const float* __restrict__ A, const float* __restrict__ W,
               float* __restrict__ out_param, int M, int Nseq)
{
    extern __shared__ float sm[];
    float* Asb[2] = { sm,              sm + 128 * GSTR };
    float* Bsb[2] = { sm + 2*128*GSTR, sm + 3*128*GSTR };

    const int tid  = threadIdx.x;
    const int lane = tid & 31;
    const int wid  = tid >> 5;
    const int wm   = wid >> 2;       // 0..1
    const int wn   = wid & 3;        // 0..3
    const int m0   = blockIdx.y * 128;
    const int n0   = blockIdx.x * 128;

    const float* Ae = (DST == 4) ? (const float*)g_AO : A;
    float* out = (DST == 0) ? g_Q : (DST == 1) ? g_K : (DST == 2) ? g_VT : out_param;

    float acc[4][4][4];
    #pragma unroll
    for (int i = 0; i < 4; i++)
        #pragma unroll
        for (int j = 0; j < 4; j++)
            #pragma unroll
            for (int r = 0; r < 4; r++) acc[i][j][r] = 0.f;

    auto load_tiles = [&](int buf, int kt) {
        const float* Ag = Ae + (size_t)m0 * 512 + kt * 32;
        const float* Wg = W  + (size_t)n0 * 512 + kt * 32;
        #pragma unroll
        for (int i = 0; i < 4; i++) {
            int idx = tid + i * 256;
            int row = idx >> 3, seg = idx & 7;
            cp16(&Asb[buf][row * GSTR + seg * 4], Ag + (size_t)row * 512 + seg * 4);
        }
        #pragma unroll
        for (int i = 0; i < 4; i++) {
            int idx = tid + i * 256;
            int row = idx >> 3, seg = idx & 7;
            cp16(&Bsb[buf][row * GSTR + seg * 4], Wg + (size_t)row * 512 + seg * 4);
        }
        CP_COMMIT();
    };

    // in-place convert to tf32 + interleave 8-chunks (one thread owns a chunk)
    auto convert = [&](float* t) {
        #pragma unroll
        for (int i = 0; i < 2; i++) {
            int ch = tid + i * 256;               // 512 chunks: 128 rows x 4
            float* p = t + (ch >> 2) * GSTR + (ch & 3) * 8;
            float4 u = *(float4*)p;
            float4 v = *(float4*)(p + 4);
            float4 w0 = make_float4(tfr(u.x), tfr(v.x), tfr(u.y), tfr(v.y));
            float4 w1 = make_float4(tfr(u.z), tfr(v.z), tfr(u.w), tfr(v.w));
            *(float4*)p       = w0;
            *(float4*)(p + 4) = w1;
        }
    };

    load_tiles(0, 0);

    for (int kt = 0; kt < 16; kt++) {
        const int buf = kt & 1;
        if (kt + 1 < 16) {
            load_tiles(buf ^ 1, kt + 1);
            asm volatile("cp.async.wait_group 1;");
        } else {
            asm volatile("cp.async.wait_group 0;");
        }
        __syncthreads();
        convert(Asb[buf]);
        convert(Bsb[buf]);
        __syncthreads();

        const float* a_s = Asb[buf];
        const float* b_s = Bsb[buf];
        const int coff = 2 * (lane & 3);
        #pragma unroll
        for (int ks = 0; ks < 4; ks++) {
            const int cc = ks * 8 + coff;
            uint32_t af[4][4];
            uint2 bf[4];
            #pragma unroll
            for (int ma = 0; ma < 4; ma++) {
                const int r = wm * 64 + ma * 16 + (lane >> 2);
                uint2 lo = *(const uint2*)&a_s[r * GSTR + cc];
                uint2 hi = *(const uint2*)&a_s[(r + 8) * GSTR + cc];
                af[ma][0] = lo.x; af[ma][1] = hi.x; af[ma][2] = lo.y; af[ma][3] = hi.y;
            }
            #pragma unroll
            for (int na = 0; na < 4; na++) {
                const int nn = wn * 32 + na * 8 + (lane >> 2);
                bf[na] = *(const uint2*)&b_s[nn * GSTR + cc];
            }
            #pragma unroll
            for (int ma = 0; ma < 4; ma++)
                #pragma unroll
                for (int na = 0; na < 4; na++)
                    mma_tf32(acc[ma][na], af[ma], bf[na].x, bf[na].y);
        }
        __syncthreads();
    }

    // epilogue
    #pragma unroll
    for (int ma = 0; ma < 4; ma++) {
        #pragma unroll
        for (int na = 0; na < 4; na++) {
            const int m = m0 + wm * 64 + ma * 16 + (lane >> 2);
            const int n = n0 + wn * 32 + na * 8 + 2 * (lane & 3);
            const float* a = acc[ma][na];
            if (DST == 0 || DST == 1) {
                // head-split, hd-interleaved, tf32-rounded
                const int bb = m / Nseq;
                const int nn = m - bb * Nseq;
                const int h  = n >> 6;
                const int hd = n & 63;
                const int hb = hd & ~7, j = hd & 7;
                const int p1 = ilpos(j), p2 = ilpos(j + 1);
                float* base = out + (((size_t)bb * H_ + h) * Nseq) * HD_;
                base[(size_t)nn * HD_ + hb + p1]       = tfr(a[0]);
                base[(size_t)nn * HD_ + hb + p2]       = tfr(a[1]);
                base[(size_t)(nn + 8) * HD_ + hb + p1] = tfr(a[2]);
                base[(size_t)(nn + 8) * HD_ + hb + p2] = tfr(a[3]);
            } else if (DST == 2) {
                // V transposed: [b][h][hd][nkv], kv-interleaved, tf32-rounded
                const int bb = m / Nseq;
                const int kv = m - bb * Nseq;
                const int h  = n >> 6;
                const int hd = n & 63;
                const int kvp = (kv & ~7) | ilpos(kv & 7);
                float* base = out + (((size_t)bb * H_ + h) * HD_ + hd) * NKV_;
                base[kvp]            = tfr(a[0]);
                base[NKV_ + kvp]     = tfr(a[1]);          // hd+1
                base[kvp + 8]        = tfr(a[2]);          // kv+8 (same j, next chunk)
                base[NKV_ + kvp + 8] = tfr(a[3]);
            } else {
                *(float2*)(out + (size_t)m * 512 + n)       = make_float2(a[0], a[1]);
                *(float2*)(out + (size_t)(m + 8) * 512 + n) = make_float2(a[2], a[3]);
            }
        }
    }
}

// =======================================================================
// Flash attention with additive bias. Operands arrive tf32-rounded and
// chunk-interleaved -> zero cvt for Q/K/V, all fragment loads are LDS.64.
// CTA: one (b, h, q-tile of 128). 8 warps x 16 rows. KV tile = 64.
// =======================================================================
#define ASTR 72   // row stride, mod 32 words == 8 -> phase-conflict-free
#define ATT_SMEM_FLOATS ((128 + 64 + 64 + 128) * ASTR)

__global__ __launch_bounds__(256, 2)
void attn_tf32(const float* __restrict__ pos_bias)
{
    extern __shared__ float sm[];
    float*    Qs = sm;                       // 128 x 72 (hd-interleaved)
    float*    Ks = Qs + 128 * ASTR;          // 64 x 72  (hd-interleaved)
    float*    Vs = Ks + 64 * ASTR;           // 64 hd-rows x 72 (kv-interleaved)
    float*    Ps = Vs + 64 * ASTR;           // 128 x 72 (normal layout, tf32 bits)
    uint32_t* Pu = (uint32_t*)Ps;

    const int tid  = threadIdx.x;
    const int lane = tid & 31;
    const int wid  = tid >> 5;

    const int bx = blockIdx.x;
    const int qt = bx & 7;
    const int h  = (bx >> 3) & 7;
    const int b  = bx >> 6;

    const int rloc   = wid * 16 + (lane >> 2);
    const int q0     = qt * 128 + rloc;
    const int rbase  = rloc * ASTR;
    const int rbase8 = rbase + 8 * ASTR;
    const int coff   = 2 * (lane & 3);

    float o[8][4];
    #pragma unroll
    for (int na = 0; na < 8; na++)
        #pragma unroll
        for (int r = 0; r < 4; r++) o[na][r] = 0.f;
    float m_0 = -1e30f, m_1 = -1e30f, l_0 = 0.f, l_1 = 0.f;

    // load Q tile (128 x 64) once — already interleaved+rounded
    {
        const float* Qg = g_Q + (((size_t)b * H_ + h) * NQ_ + (size_t)qt * 128) * HD_;
        #pragma unroll
        for (int i = 0; i < 8; i++) {
            int idx = tid + i * 256;
            int row = idx >> 4, seg = idx & 15;
            cp16(&Qs[row * ASTR + seg * 4], Qg + (size_t)row * HD_ + seg * 4);
        }
        CP_COMMIT();
    }

    const float* Kg0 = g_K  + (((size_t)b * H_ + h) * NKV_) * HD_;
    const float* Vg0 = g_VT + (((size_t)b * H_ + h) * HD_) * NKV_;

    for (int kvt = 0; kvt < NKV_ / 64; kvt++) {
        // load K tile (64 kv-rows x 64) and VT tile (64 hd-rows x 64 kv)
        {
            const float* Kg = Kg0 + (size_t)kvt * 64 * HD_;
            const float* Vg = Vg0 + (size_t)kvt * 64;     // row stride NKV_
            #pragma unroll
            for (int i = 0; i < 4; i++) {
                int idx = tid + i * 256;
                int row = idx >> 4, seg = idx & 15;
                cp16(&Ks[row * ASTR + seg * 4], Kg + (size_t)row * HD_ + seg * 4);
            }
            #pragma unroll
            for (int i = 0; i < 4; i++) {
                int idx = tid + i * 256;
                int row = idx >> 4, seg = idx & 15;
                cp16(&Vs[row * ASTR + seg * 4], Vg + (size_t)row * NKV_ + seg * 4);
            }
            CP_COMMIT();
        }
        asm volatile("cp.async.wait_group 0;");
        __syncthreads();

        // ---- S = Q @ K^T (16 x 64 per warp), all LDS.64, no cvt ----
        float s[8][4];
        #pragma unroll
        for (int na = 0; na < 8; na++)
            #pragma unroll
            for (int r = 0; r < 4; r++) s[na][r] = 0.f;

        #pragma unroll
        for (int ks = 0; ks < 8; ks++) {
            const int cc = ks * 8 + coff;
            uint2 qlo = *(const uint2*)&Qs[rbase  + cc];
            uint2 qhi = *(const uint2*)&Qs[rbase8 + cc];
            uint32_t qa[4] = { qlo.x, qhi.x, qlo.y, qhi.y };
            #pragma unroll
            for (int na = 0; na < 8; na++) {
                const int nn = na * 8 + (lane >> 2);
                uint2 kb = *(const uint2*)&Ks[nn * ASTR + cc];
                mma_tf32(s[na], qa, kb.x, kb.y);
            }
        }

        // ---- add bias ----
        {
            const float* bias_base = pos_bias + ((size_t)h * NQ_ + q0) * NKV_ + (size_t)kvt * 64;
            #pragma unroll
            for (int na = 0; na < 8; na++) {
                const int cb = na * 8 + coff;
                float2 blo = *(const float2*)(bias_base + cb);
                float2 bhi = *(const float2*)(bias_base + (size_t)8 * NKV_ + cb);
                s[na][0] += blo.x; s[na][1] += blo.y;
                s[na][2] += bhi.x; s[na][3] += bhi.y;
            }
        }

        // ---- online softmax ----
        float rmax0 = -1e30f, rmax1 = -1e30f;
        #pragma unroll
        for (int na = 0; na < 8; na++) {
            rmax0 = fmaxf(rmax0, fmaxf(s[na][0], s[na][1]));
            rmax1 = fmaxf(rmax1, fmaxf(s[na][2], s[na][3]));
        }
        rmax0 = fmaxf(rmax0, __shfl_xor_sync(0xffffffffu, rmax0, 1));
        rmax0 = fmaxf(rmax0, __shfl_xor_sync(0xffffffffu, rmax0, 2));
        rmax1 = fmaxf(rmax1, __shfl_xor_sync(0xffffffffu, rmax1, 1));
        rmax1 = fmaxf(rmax1, __shfl_xor_sync(0xffffffffu, rmax1, 2));

        const float mn0 = fmaxf(m_0, rmax0);
        const float mn1 = fmaxf(m_1, rmax1);
        const float al0 = __expf(m_0 - mn0);
        const float al1 = __expf(m_1 - mn1);
        m_0 = mn0; m_1 = mn1;

        float rs0 = 0.f, rs1 = 0.f;
        #pragma unroll
        for (int na = 0; na < 8; na++) {
            s[na][0] = __expf(s[na][0] - mn0); rs0 += s[na][0];
            s[na][1] = __expf(s[na][1] - mn0); rs0 += s[na][1];
            s[na][2] = __expf(s[na][2] - mn1); rs1 += s[na][2];
            s[na][3] = __expf(s[na][3] - mn1); rs1 += s[na][3];
        }
        rs0 += __shfl_xor_sync(0xffffffffu, rs0, 1);
        rs0 += __shfl_xor_sync(0xffffffffu, rs0, 2);
        rs1 += __shfl_xor_sync(0xffffffffu, rs1, 1);
        rs1 += __shfl_xor_sync(0xffffffffu, rs1, 2);
        l_0 = l_0 * al0 + rs0;
        l_1 = l_1 * al1 + rs1;

        #pragma unroll
        for (int na = 0; na < 8; na++) {
            o[na][0] *= al0; o[na][1] *= al0;
            o[na][2] *= al1; o[na][3] *= al1;
        }

        // ---- write P (tf32 bits) to smem, warp-private rows, STS.64 ----
        __syncwarp();
        #pragma unroll
        for (int na = 0; na < 8; na++) {
            const int cb = na * 8 + coff;
            uint2 w0 = { f2tf32(s[na][0]), f2tf32(s[na][1]) };
            uint2 w1 = { f2tf32(s[na][2]), f2tf32(s[na][3]) };
            *(uint2*)&Pu[rbase  + cb] = w0;
            *(uint2*)&Pu[rbase8 + cb] = w1;
        }
        __syncwarp();

        // ---- O += P @ V^T  (VT kv-interleaved -> LDS.64 B fragments) ----
        #pragma unroll
        for (int ks = 0; ks < 8; ks++) {
            const int pc = ks * 8 + (lane & 3);
            const int cc = ks * 8 + coff;
            uint32_t pa[4];
            pa[0] = Pu[rbase  + pc];
            pa[1] = Pu[rbase8 + pc];
            pa[2] = Pu[rbase  + pc + 4];
            pa[3] = Pu[rbase8 + pc + 4];
            #pragma unroll
            for (int na = 0; na < 8; na++) {
                const int nn = na * 8 + (lane >> 2);
                uint2 vb = *(const uint2*)&Vs[nn * ASTR + cc];
                mma_tf32(o[na], pa, vb.x, vb.y);
            }
        }
        __syncthreads();   // before next K/V overwrite
    }

    // ---- finalize ----
    const float inv0 = 1.0f / l_0;
    const float inv1 = 1.0f / l_1;
    #pragma unroll
    for (int na = 0; na < 8; na++) {
        const int col = h * HD_ + na * 8 + coff;
        *(float2*)(g_AO + ((size_t)b * NQ_ + q0) * D_ + col) =
            make_float2(o[na][0] * inv0, o[na][1] * inv0);
        *(float2*)(g_AO + ((size_t)b * NQ_ + q0 + 8) * D_ + col) =
            make_float2(o[na][2] * inv1, o[na][3] * inv1);
    }
}

// =======================================================================
// launch
// =======================================================================
#define GEMM_SMEM (4 * 128 * GSTR * sizeof(float))          // 81920 B
#define ATT_SMEM  (ATT_SMEM_FLOATS * sizeof(float))         // 110592 B

extern "C" void kernel_launch(void* const* d_in, const int* in_sizes, int n_in,
                              void* d_out, int out_size)
{
    const float* x        = (const float*)d_in[0];
    const float* enc      = (const float*)d_in[1];
    const float* pos_bias = (const float*)d_in[2];
    const float* Wq       = (const float*)d_in[3];
    const float* Wk       = (const float*)d_in[4];
    const float* Wv       = (const float*)d_in[5];
    const float* Wo       = (const float*)d_in[6];
    float* out = (float*)d_out;

    cudaFuncSetAttribute(gemm_tf32<0>, cudaFuncAttributeMaxDynamicSharedMemorySize, GEMM_SMEM);
    cudaFuncSetAttribute(gemm_tf32<1>, cudaFuncAttributeMaxDynamicSharedMemorySize, GEMM_SMEM);
    cudaFuncSetAttribute(gemm_tf32<2>, cudaFuncAttributeMaxDynamicSharedMemorySize, GEMM_SMEM);
    cudaFuncSetAttribute(gemm_tf32<4>, cudaFuncAttributeMaxDynamicSharedMemorySize, GEMM_SMEM);
    cudaFuncSetAttribute(attn_tf32,    cudaFuncAttributeMaxDynamicSharedMemorySize, ATT_SMEM);

    // projections -> head-split tf32-rounded interleaved scratch
    gemm_tf32<0><<<dim3(4, 64),  256, GEMM_SMEM>>>(x,   Wq, nullptr, B_ * NQ_,  NQ_);
    gemm_tf32<1><<<dim3(4, 128), 256, GEMM_SMEM>>>(enc, Wk, nullptr, B_ * NKV_, NKV_);
    gemm_tf32<2><<<dim3(4, 128), 256, GEMM_SMEM>>>(enc, Wv, nullptr, B_ * NKV_, NKV_);
    // attention
    attn_tf32<<<B_ * H_ * (NQ_ / 128), 256, ATT_SMEM>>>(pos_bias);
    // output projection (A = g_AO device-side)
    gemm_tf32<4><<<dim3(4, 64), 256, GEMM_SMEM>>>(nullptr, Wo, out, B_ * NQ_, NQ_);
}

// round 7
// speedup vs baseline: 1.9462x; 1.9462x over previous
#include <cuda_runtime.h>
#include <cuda_fp16.h>
#include <cstdint>

#define B_  8
#define H_  8
#define NQ_ 1024
#define NKV_ 2048
#define D_  512
#define HD_ 64

// ---------------- scratch (static __device__, no allocs) ----------------
__device__ __half g_Qh [B_ * H_ * NQ_  * HD_];   // [b][h][q][hd]   8 MB
__device__ __half g_Kh [B_ * H_ * NKV_ * HD_];   // [b][h][kv][hd] 16 MB
__device__ __half g_Vh [B_ * H_ * NKV_ * HD_];   // [b][h][kv][hd] 16 MB
__device__ float  g_AO [B_ * NQ_ * D_];          // [b][q][d]      16 MB (fp32)

// ---------------- helpers ----------------
__device__ __forceinline__ uint32_t smem_u32(const void* p) {
    uint32_t a;
    asm("{ .reg .u64 t; cvta.to.shared.u64 t, %1; cvt.u32.u64 %0, t; }" : "=r"(a) : "l"(p));
    return a;
}
__device__ __forceinline__ void cp16s(uint32_t d, const void* src) {
    asm volatile("cp.async.cg.shared.global [%0], [%1], 16;" :: "r"(d), "l"(src));
}
#define CP_COMMIT() asm volatile("cp.async.commit_group;")

__device__ __forceinline__ void mma_f16(float* c, const uint32_t* a, uint32_t b0, uint32_t b1) {
    asm volatile(
        "mma.sync.aligned.m16n8k16.row.col.f32.f16.f16.f32 "
        "{%0,%1,%2,%3}, {%4,%5,%6,%7}, {%8,%9}, {%0,%1,%2,%3};"
        : "+f"(c[0]), "+f"(c[1]), "+f"(c[2]), "+f"(c[3])
        : "r"(a[0]), "r"(a[1]), "r"(a[2]), "r"(a[3]), "r"(b0), "r"(b1));
}
__device__ __forceinline__ void ldsm4(uint32_t* r, uint32_t addr) {
    asm volatile("ldmatrix.sync.aligned.m8n8.x4.shared.b16 {%0,%1,%2,%3}, [%4];"
                 : "=r"(r[0]), "=r"(r[1]), "=r"(r[2]), "=r"(r[3]) : "r"(addr));
}
__device__ __forceinline__ void ldsm4t(uint32_t* r, uint32_t addr) {
    asm volatile("ldmatrix.sync.aligned.m8n8.x4.trans.shared.b16 {%0,%1,%2,%3}, [%4];"
                 : "=r"(r[0]), "=r"(r[1]), "=r"(r[2]), "=r"(r[3]) : "r"(addr));
}
__device__ __forceinline__ uint32_t h2pack(float a, float b) {
    __half2 h = __floats2half2_rn(a, b);
    return *(uint32_t*)&h;
}

// =======================================================================
// fp16 GEMM: out[m][n] = sum_k A[m][k] * W[n][k]   (M x 512 @ 512 x 512)
// DST 0: g_Qh, 1: g_Kh, 2: g_Vh (natural [b][h][seq][hd] half)
// DST 3: fp32 out, A = g_AO (fp32, converted during smem staging).
// smem fp16 tiles [128][40] halves (80B rows, odd x 16B -> conflict-free).
// =======================================================================
#define GSTB 80
#define GEMM_SMEM (4 * 128 * GSTB)          // A0 A1 W0 W1 = 40960 B

template<int DST>
__global__ __launch_bounds__(256, 2)
void gemm_f16(const float* __restrict__ A, const float* __restrict__ W,
              float* __restrict__ out_param, int M, int Nseq)
{
    extern __shared__ char smem[];
    const uint32_t sb = smem_u32(smem);
    const uint32_t AO[2] = { 0u, 10240u };
    const uint32_t WO[2] = { 20480u, 30720u };

    const int tid  = threadIdx.x;
    const int lane = tid & 31;
    const int wid  = tid >> 5;
    const int wm   = wid >> 2;
    const int wn   = wid & 3;
    const int m0   = blockIdx.y * 128;
    const int n0   = blockIdx.x * 128;

    const uint32_t a_l = (uint32_t)(lane & 15) * GSTB + (uint32_t)(lane >> 4) * 16;
    const uint32_t b_l = (uint32_t)((lane & 7) + ((lane >> 4) & 1) * 8) * GSTB
                       + (uint32_t)((lane >> 3) & 1) * 16;

    float acc[4][4][4];
    #pragma unroll
    for (int i = 0; i < 4; i++)
        #pragma unroll
        for (int j = 0; j < 4; j++)
            #pragma unroll
            for (int r = 0; r < 4; r++) acc[i][j][r] = 0.f;

    const float* Ae = (DST == 3) ? (const float*)g_AO : A;
    const float* Wg = W + (size_t)n0 * 512;

    float4 ar[2][2]; float4 wr[2][2];

    auto ldg = [&](int kt) {
        #pragma unroll
        for (int i = 0; i < 2; i++) {
            int idx = tid + i * 256;
            int row = idx >> 2, kg = (idx & 3) * 8;
            const float* p = Ae + (size_t)(m0 + row) * 512 + kt * 32 + kg;
            ar[i][0] = *(const float4*)p;
            ar[i][1] = *(const float4*)(p + 4);
            const float* q = Wg + (size_t)row * 512 + kt * 32 + kg;
            wr[i][0] = *(const float4*)q;
            wr[i][1] = *(const float4*)(q + 4);
        }
    };
    auto sts = [&](int buf) {
        #pragma unroll
        for (int i = 0; i < 2; i++) {
            int idx = tid + i * 256;
            int row = idx >> 2, kg = (idx & 3) * 8;
            __half2 ha[4] = {
                __floats2half2_rn(ar[i][0].x, ar[i][0].y),
                __floats2half2_rn(ar[i][0].z, ar[i][0].w),
                __floats2half2_rn(ar[i][1].x, ar[i][1].y),
                __floats2half2_rn(ar[i][1].z, ar[i][1].w) };
            *(uint4*)(smem + AO[buf] + (size_t)row * GSTB + kg * 2) = *(uint4*)ha;
            __half2 hw[4] = {
                __floats2half2_rn(wr[i][0].x, wr[i][0].y),
                __floats2half2_rn(wr[i][0].z, wr[i][0].w),
                __floats2half2_rn(wr[i][1].x, wr[i][1].y),
                __floats2half2_rn(wr[i][1].z, wr[i][1].w) };
            *(uint4*)(smem + WO[buf] + (size_t)row * GSTB + kg * 2) = *(uint4*)hw;
        }
    };

    ldg(0);
    sts(0);
    __syncthreads();

    for (int kt = 0; kt < 16; kt++) {
        const int buf = kt & 1;
        if (kt < 15) ldg(kt + 1);

        const uint32_t Ab = sb + AO[buf] + (uint32_t)(wm * 64) * GSTB + a_l;
        const uint32_t Wb = sb + WO[buf] + (uint32_t)(wn * 32) * GSTB + b_l;
        #pragma unroll
        for (int ks = 0; ks < 2; ks++) {
            uint32_t bm[2][4];
            #pragma unroll
            for (int nb = 0; nb < 2; nb++)
                ldsm4(bm[nb], Wb + (uint32_t)(nb * 16) * GSTB + ks * 32);
            #pragma unroll
            for (int ma = 0; ma < 4; ma++) {
                uint32_t a[4];
                ldsm4(a, Ab + (uint32_t)(ma * 16) * GSTB + ks * 32);
                #pragma unroll
                for (int nb = 0; nb < 2; nb++) {
                    mma_f16(acc[ma][nb * 2],     a, bm[nb][0], bm[nb][1]);
                    mma_f16(acc[ma][nb * 2 + 1], a, bm[nb][2], bm[nb][3]);
                }
            }
        }
        if (kt < 15) {
            sts(buf ^ 1);
            __syncthreads();
        }
    }

    // epilogue
    __half* dsth = (DST == 0) ? g_Qh : (DST == 1) ? g_Kh : g_Vh;
    #pragma unroll
    for (int ma = 0; ma < 4; ma++) {
        #pragma unroll
        for (int na = 0; na < 4; na++) {
            const int m = m0 + wm * 64 + ma * 16 + (lane >> 2);
            const int n = n0 + wn * 32 + na * 8 + 2 * (lane & 3);
            const float* a = acc[ma][na];
            if (DST != 3) {
                const int bb = m / Nseq;
                const int nn = m - bb * Nseq;
                const int h  = n >> 6;
                const int hd = n & 63;
                __half* base = dsth + (((size_t)bb * H_ + h) * Nseq + nn) * HD_ + hd;
                *(__half2*)base              = __floats2half2_rn(a[0], a[1]);
                *(__half2*)(base + 8 * HD_)  = __floats2half2_rn(a[2], a[3]);
            } else {
                *(float2*)(out_param + (size_t)m * 512 + n)       = make_float2(a[0], a[1]);
                *(float2*)(out_param + (size_t)(m + 8) * 512 + n) = make_float2(a[2], a[3]);
            }
        }
    }
}

// =======================================================================
// fp16 flash attention, additive bias, ONLINE SOFTMAX (P in (0,1] -> no
// fp16 overflow). CTA: (b, h, 128-q tile). 8 warps x m16, full n64 each.
// P lives in registers (C-frag layout == A-frag layout). V via
// ldmatrix.trans. KV tile 64, double-buffered.
// =======================================================================
#define ASTB 144
#define ATT_SMEM (128 * ASTB + 4 * 64 * ASTB)      // Q + K0 K1 V0 V1 = 55296

__global__ __launch_bounds__(256, 2)
void attn_f16(const float* __restrict__ pos_bias)
{
    extern __shared__ char smem[];
    const uint32_t sb  = smem_u32(smem);
    const uint32_t SQ  = sb;
    const uint32_t SK0 = SQ  + 128 * ASTB;
    const uint32_t SK1 = SK0 + 64 * ASTB;
    const uint32_t SV0 = SK1 + 64 * ASTB;
    const uint32_t SV1 = SV0 + 64 * ASTB;

    const int tid  = threadIdx.x;
    const int lane = tid & 31;
    const int wid  = tid >> 5;
    const int bx = blockIdx.x;
    const int qt = bx & 7;
    const int h  = (bx >> 3) & 7;
    const int b  = bx >> 6;
    const int mrow = wid * 16;

    const uint32_t q_l = (uint32_t)(mrow + (lane & 15)) * ASTB + (uint32_t)(lane >> 4) * 16;
    const uint32_t k_l = (uint32_t)((lane & 7) + ((lane >> 4) & 1) * 8) * ASTB
                       + (uint32_t)((lane >> 3) & 1) * 16;
    const uint32_t v_l = (uint32_t)((lane & 7) + ((lane >> 3) & 1) * 8) * ASTB
                       + (uint32_t)((lane >> 4) & 1) * 16;

    const __half* Qg  = g_Qh + (((size_t)b * H_ + h) * NQ_ + (size_t)qt * 128) * HD_;
    const __half* Kg0 = g_Kh + (((size_t)b * H_ + h) * NKV_) * HD_;
    const __half* Vg0 = g_Vh + (((size_t)b * H_ + h) * NKV_) * HD_;

    // prologue: Q (1024 x 16B), K0, V0 (512 x 16B each)
    #pragma unroll
    for (int i = 0; i < 4; i++) {
        int idx = tid + i * 256, r = idx >> 3, s = idx & 7;
        cp16s(SQ + (uint32_t)r * ASTB + s * 16, Qg + (size_t)r * HD_ + s * 8);
    }
    #pragma unroll
    for (int i = 0; i < 2; i++) {
        int idx = tid + i * 256, r = idx >> 3, s = idx & 7;
        cp16s(SK0 + (uint32_t)r * ASTB + s * 16, Kg0 + (size_t)r * HD_ + s * 8);
        cp16s(SV0 + (uint32_t)r * ASTB + s * 16, Vg0 + (size_t)r * HD_ + s * 8);
    }
    CP_COMMIT();

    float o[8][4];
    #pragma unroll
    for (int na = 0; na < 8; na++)
        #pragma unroll
        for (int r = 0; r < 4; r++) o[na][r] = 0.f;
    float m_0 = -1e30f, m_1 = -1e30f, l0 = 0.f, l1 = 0.f;

    const float* bias_r0 = pos_bias
        + ((size_t)h * NQ_ + (size_t)qt * 128 + mrow + (lane >> 2)) * NKV_ + 2 * (lane & 3);

    for (int t = 0; t < 32; t++) {
        const uint32_t K = (t & 1) ? SK1 : SK0;
        const uint32_t V = (t & 1) ? SV1 : SV0;
        asm volatile("cp.async.wait_group 0;");
        __syncthreads();

        if (t < 31) {
            const uint32_t NK = (t & 1) ? SK0 : SK1;
            const uint32_t NV = (t & 1) ? SV0 : SV1;
            const __half* Kg = Kg0 + (size_t)(t + 1) * 64 * HD_;
            const __half* Vg = Vg0 + (size_t)(t + 1) * 64 * HD_;
            #pragma unroll
            for (int i = 0; i < 2; i++) {
                int idx = tid + i * 256, r = idx >> 3, s = idx & 7;
                cp16s(NK + (uint32_t)r * ASTB + s * 16, Kg + (size_t)r * HD_ + s * 8);
                cp16s(NV + (uint32_t)r * ASTB + s * 16, Vg + (size_t)r * HD_ + s * 8);
            }
            CP_COMMIT();
        }

        // ---- S = Q @ K^T ----
        float s[8][4];
        #pragma unroll
        for (int na = 0; na < 8; na++)
            #pragma unroll
            for (int r = 0; r < 4; r++) s[na][r] = 0.f;

        #pragma unroll
        for (int ks = 0; ks < 4; ks++) {
            uint32_t a[4];
            ldsm4(a, SQ + q_l + ks * 32);
            #pragma unroll
            for (int nb = 0; nb < 4; nb++) {
                uint32_t bm[4];
                ldsm4(bm, K + k_l + (uint32_t)(nb * 16) * ASTB + ks * 32);
                mma_f16(s[nb * 2],     a, bm[0], bm[1]);
                mma_f16(s[nb * 2 + 1], a, bm[2], bm[3]);
            }
        }

        // ---- + bias ----
        const float* bb = bias_r0 + (size_t)t * 64;
        #pragma unroll
        for (int na = 0; na < 8; na++) {
            float2 blo = *(const float2*)(bb + na * 8);
            float2 bhi = *(const float2*)(bb + (size_t)8 * NKV_ + na * 8);
            s[na][0] += blo.x; s[na][1] += blo.y;
            s[na][2] += bhi.x; s[na][3] += bhi.y;
        }

        // ---- online softmax ----
        float rmax0 = -1e30f, rmax1 = -1e30f;
        #pragma unroll
        for (int na = 0; na < 8; na++) {
            rmax0 = fmaxf(rmax0, fmaxf(s[na][0], s[na][1]));
            rmax1 = fmaxf(rmax1, fmaxf(s[na][2], s[na][3]));
        }
        rmax0 = fmaxf(rmax0, __shfl_xor_sync(0xffffffffu, rmax0, 1));
        rmax0 = fmaxf(rmax0, __shfl_xor_sync(0xffffffffu, rmax0, 2));
        rmax1 = fmaxf(rmax1, __shfl_xor_sync(0xffffffffu, rmax1, 1));
        rmax1 = fmaxf(rmax1, __shfl_xor_sync(0xffffffffu, rmax1, 2));

        const float mn0 = fmaxf(m_0, rmax0);
        const float mn1 = fmaxf(m_1, rmax1);
        const float al0 = __expf(m_0 - mn0);
        const float al1 = __expf(m_1 - mn1);
        m_0 = mn0; m_1 = mn1;

        float rs0 = 0.f, rs1 = 0.f;
        #pragma unroll
        for (int na = 0; na < 8; na++) {
            s[na][0] = __expf(s[na][0] - mn0); rs0 += s[na][0];
            s[na][1] = __expf(s[na][1] - mn0); rs0 += s[na][1];
            s[na][2] = __expf(s[na][2] - mn1); rs1 += s[na][2];
            s[na][3] = __expf(s[na][3] - mn1); rs1 += s[na][3];
        }
        l0 = l0 * al0 + rs0;
        l1 = l1 * al1 + rs1;

        #pragma unroll
        for (int na = 0; na < 8; na++) {
            o[na][0] *= al0; o[na][1] *= al0;
            o[na][2] *= al1; o[na][3] *= al1;
        }

        // ---- O += P @ V  (P packed from registers, V via ldmatrix.trans) ----
        #pragma unroll
        for (int ks = 0; ks < 4; ks++) {
            uint32_t pa[4];
            pa[0] = h2pack(s[2*ks][0],   s[2*ks][1]);
            pa[1] = h2pack(s[2*ks][2],   s[2*ks][3]);
            pa[2] = h2pack(s[2*ks+1][0], s[2*ks+1][1]);
            pa[3] = h2pack(s[2*ks+1][2], s[2*ks+1][3]);
            #pragma unroll
            for (int nb = 0; nb < 4; nb++) {
                uint32_t bm[4];
                ldsm4t(bm, V + v_l + (uint32_t)(ks * 16) * ASTB + nb * 32);
                mma_f16(o[nb * 2],     pa, bm[0], bm[1]);
                mma_f16(o[nb * 2 + 1], pa, bm[2], bm[3]);
            }
        }
        __syncthreads();
    }

    // ---- finalize: reduce l over quad lanes, scale, store fp32 AO ----
    l0 += __shfl_xor_sync(0xffffffffu, l0, 1);
    l0 += __shfl_xor_sync(0xffffffffu, l0, 2);
    l1 += __shfl_xor_sync(0xffffffffu, l1, 1);
    l1 += __shfl_xor_sync(0xffffffffu, l1, 2);
    const float inv0 = 1.0f / l0;
    const float inv1 = 1.0f / l1;

    const size_t r0 = (size_t)b * NQ_ + (size_t)qt * 128 + mrow + (lane >> 2);
    #pragma unroll
    for (int na = 0; na < 8; na++) {
        const int col = h * HD_ + na * 8 + 2 * (lane & 3);
        *(float2*)(g_AO + r0 * D_ + col) =
            make_float2(o[na][0] * inv0, o[na][1] * inv0);
        *(float2*)(g_AO + (r0 + 8) * D_ + col) =
            make_float2(o[na][2] * inv1, o[na][3] * inv1);
    }
}

// =======================================================================
// launch
// =======================================================================
extern "C" void kernel_launch(void* const* d_in, const int* in_sizes, int n_in,
                              void* d_out, int out_size)
{
    const float* x        = (const float*)d_in[0];
    const float* enc      = (const float*)d_in[1];
    const float* pos_bias = (const float*)d_in[2];
    const float* Wq       = (const float*)d_in[3];
    const float* Wk       = (const float*)d_in[4];
    const float* Wv       = (const float*)d_in[5];
    const float* Wo       = (const float*)d_in[6];
    float* out = (float*)d_out;

    cudaFuncSetAttribute(gemm_f16<0>, cudaFuncAttributeMaxDynamicSharedMemorySize, GEMM_SMEM);
    cudaFuncSetAttribute(gemm_f16<1>, cudaFuncAttributeMaxDynamicSharedMemorySize, GEMM_SMEM);
    cudaFuncSetAttribute(gemm_f16<2>, cudaFuncAttributeMaxDynamicSharedMemorySize, GEMM_SMEM);
    cudaFuncSetAttribute(gemm_f16<3>, cudaFuncAttributeMaxDynamicSharedMemorySize, GEMM_SMEM);
    cudaFuncSetAttribute(attn_f16,    cudaFuncAttributeMaxDynamicSharedMemorySize, ATT_SMEM);

    gemm_f16<0><<<dim3(4, 64),  256, GEMM_SMEM>>>(x,   Wq, nullptr, B_ * NQ_,  NQ_);
    gemm_f16<1><<<dim3(4, 128), 256, GEMM_SMEM>>>(enc, Wk, nullptr, B_ * NKV_, NKV_);
    gemm_f16<2><<<dim3(4, 128), 256, GEMM_SMEM>>>(enc, Wv, nullptr, B_ * NKV_, NKV_);
    attn_f16<<<B_ * H_ * (NQ_ / 128), 256, ATT_SMEM>>>(pos_bias);
    gemm_f16<3><<<dim3(4, 64), 256, GEMM_SMEM>>>(nullptr, Wo, out, B_ * NQ_, NQ_);
}